// round 1
// baseline (speedup 1.0000x reference)
#include <cuda_runtime.h>
#include <cuda_bf16.h>
#include <math.h>

// Problem constants (fixed shapes: B=4, S=4096, D=1024, WINDOW=128, stride 64)
#define BB   4
#define SS   4096
#define DD   1024
#define NW   63              // number of windows
#define BSD  (BB*SS*DD)      // 16,777,216 floats

typedef unsigned long long ull;

// ---------------- scratch (device globals; no allocation allowed) ----------
__device__ float g_q[BSD];
__device__ float g_k[BSD];
__device__ float g_v[BSD];
__device__ float g_acc[BSD];

// ---------------- f32x2 packed-FMA helpers ---------------------------------
__device__ __forceinline__ ull pack2(float lo, float hi) {
    ull r; asm("mov.b64 %0, {%1,%2};" : "=l"(r) : "f"(lo), "f"(hi)); return r;
}
__device__ __forceinline__ void unpack2(ull v, float &lo, float &hi) {
    asm("mov.b64 {%0,%1}, %2;" : "=f"(lo), "=f"(hi) : "l"(v));
}
__device__ __forceinline__ void fma2(ull &c, ull a, ull b) {
    asm("fma.rn.f32x2 %0, %1, %2, %0;" : "+l"(c) : "l"(a), "l"(b));
}

// ---------------- zero kernel ----------------------------------------------
__global__ void zero_f4(float4* __restrict__ p, int n4) {
    int i = blockIdx.x * blockDim.x + threadIdx.x;
    int stride = gridDim.x * blockDim.x;
    float4 z = make_float4(0.f, 0.f, 0.f, 0.f);
    for (; i < n4; i += stride) p[i] = z;
}

// ---------------- 128x128x8 SGEMM with bias (+ optional row scaling) -------
// C[M,N] = scale(A)[M,K] * W[K,N] + bias[N]
// 256 threads, each computes 8x8 (split 4+4 in each dim), f32x2 packed FMA.
template<bool SCALE>
__global__ void __launch_bounds__(256) sgemm_bias(
    const float* __restrict__ A, const float* __restrict__ Wt,
    const float* __restrict__ bias, float* __restrict__ C,
    int M, int N, int K)
{
    __shared__ float As[8][128];
    __shared__ float Bs[8][128];

    const int t  = threadIdx.x;
    const int tx = t & 15;          // 16 col-groups
    const int ty = t >> 4;          // 16 row-groups
    const long m0 = (long)blockIdx.y * 128;
    const long n0 = (long)blockIdx.x * 128;

    const int arow = t >> 1;        // 0..127
    const int acol = (t & 1) * 4;   // 0 or 4
    const int brow = t >> 5;        // 0..7
    const int bcol = (t & 31) * 4;  // 0..124

    float ascale = 1.f;
    if (SCALE) {
        int sr = (int)((m0 + arow) & (SS - 1));
        ascale = (sr < 64 || sr >= SS - 64) ? 1.f : 0.5f;
    }

    const float* Ap = A  + (m0 + arow) * (long)K + acol;
    const float* Bp = Wt + (long)brow * N + n0 + bcol;

    float4 av = *(const float4*)Ap;
    float4 bv = *(const float4*)Bp;

    ull c2[8][4];
#pragma unroll
    for (int i = 0; i < 8; i++)
#pragma unroll
        for (int j = 0; j < 4; j++) c2[i][j] = 0ull;

    for (int k0 = 0; k0 < K; k0 += 8) {
        float4 au = av;
        if (SCALE) { au.x *= ascale; au.y *= ascale; au.z *= ascale; au.w *= ascale; }
        As[acol + 0][arow] = au.x;
        As[acol + 1][arow] = au.y;
        As[acol + 2][arow] = au.z;
        As[acol + 3][arow] = au.w;
        *(float4*)&Bs[brow][bcol] = bv;
        __syncthreads();

        if (k0 + 8 < K) {                      // prefetch next tiles
            av = *(const float4*)(Ap + k0 + 8);
            bv = *(const float4*)(Bp + (long)(k0 + 8) * N);
        }

#pragma unroll
        for (int kk = 0; kk < 8; kk++) {
            float4 b0 = *(const float4*)&Bs[kk][tx * 4];
            float4 b1 = *(const float4*)&Bs[kk][64 + tx * 4];
            ull p00 = ((ull*)&b0)[0], p01 = ((ull*)&b0)[1];
            ull p10 = ((ull*)&b1)[0], p11 = ((ull*)&b1)[1];
#pragma unroll
            for (int i = 0; i < 8; i++) {
                float a = (i < 4) ? As[kk][ty * 4 + i] : As[kk][64 + ty * 4 + (i - 4)];
                ull a2 = pack2(a, a);
                fma2(c2[i][0], a2, p00);
                fma2(c2[i][1], a2, p01);
                fma2(c2[i][2], a2, p10);
                fma2(c2[i][3], a2, p11);
            }
        }
        __syncthreads();
    }

    // epilogue: +bias, store
#pragma unroll
    for (int i = 0; i < 8; i++) {
        long row = m0 + ((i < 4) ? (ty * 4 + i) : (64 + ty * 4 + (i - 4)));
        float* cp = C + row * (long)N + n0;
        const float* bp = bias + n0;
        float x0, x1, x2, x3, y0, y1, y2, y3;
        unpack2(c2[i][0], x0, x1); unpack2(c2[i][1], x2, x3);
        unpack2(c2[i][2], y0, y1); unpack2(c2[i][3], y2, y3);
        float4 r0 = make_float4(x0 + bp[tx * 4 + 0], x1 + bp[tx * 4 + 1],
                                x2 + bp[tx * 4 + 2], x3 + bp[tx * 4 + 3]);
        float4 r1 = make_float4(y0 + bp[64 + tx * 4 + 0], y1 + bp[64 + tx * 4 + 1],
                                y2 + bp[64 + tx * 4 + 2], y3 + bp[64 + tx * 4 + 3]);
        *(float4*)&cp[tx * 4]      = r0;
        *(float4*)&cp[64 + tx * 4] = r1;
    }
}

// ---------------- windowed attention ---------------------------------------
// Block = (window w, query-half qh): 64 query rows x 128 keys, d=1024.
// scores -> softmax in SMEM -> P*V in 8 column chunks -> atomicAdd into acc.
__global__ void __launch_bounds__(256) window_attn(
    const float* __restrict__ q, const float* __restrict__ k,
    const float* __restrict__ v, float* __restrict__ acc)
{
    __shared__ float P[64][132];     // scores / probs (padded)
    __shared__ float Ts0[8][128];    // K tile (transposed) / V tile (direct)
    __shared__ float Ts1[8][64];     // Q tile (transposed)

    const int t  = threadIdx.x;
    const int tx = t & 15;
    const int ty = t >> 4;           // 0..15 -> 4 rows each (64 rows)
    const int w  = blockIdx.x >> 1;
    const int qh = blockIdx.x & 1;
    const int b  = blockIdx.y;
    const long base = (long)b * SS * DD;
    const int s0 = w * 64;           // window start (keys: s0 .. s0+127)
    const int q0 = s0 + qh * 64;     // query rows for this block

    // ---- phase 1: S = Q * K^T / 8 over d=1024 ----
    const int lrow = t >> 1;         // 0..127
    const int lcol = (t & 1) * 4;    // 0 or 4
    const float* Qp = q + base + (long)(q0 + lrow) * DD + lcol;   // valid t<128
    const float* Kp = k + base + (long)(s0 + lrow) * DD + lcol;

    float4 kv = *(const float4*)Kp;
    float4 qv = make_float4(0, 0, 0, 0);
    if (t < 128) qv = *(const float4*)Qp;

    ull s2[4][4];
#pragma unroll
    for (int i = 0; i < 4; i++)
#pragma unroll
        for (int j = 0; j < 4; j++) s2[i][j] = 0ull;

    for (int k0 = 0; k0 < DD; k0 += 8) {
        if (t < 128) {
            Ts1[lcol + 0][lrow] = qv.x; Ts1[lcol + 1][lrow] = qv.y;
            Ts1[lcol + 2][lrow] = qv.z; Ts1[lcol + 3][lrow] = qv.w;
        }
        Ts0[lcol + 0][lrow] = kv.x; Ts0[lcol + 1][lrow] = kv.y;
        Ts0[lcol + 2][lrow] = kv.z; Ts0[lcol + 3][lrow] = kv.w;
        __syncthreads();

        if (k0 + 8 < DD) {
            kv = *(const float4*)(Kp + k0 + 8);
            if (t < 128) qv = *(const float4*)(Qp + k0 + 8);
        }

#pragma unroll
        for (int kk = 0; kk < 8; kk++) {
            float4 b0 = *(const float4*)&Ts0[kk][tx * 4];
            float4 b1 = *(const float4*)&Ts0[kk][64 + tx * 4];
            ull p00 = ((ull*)&b0)[0], p01 = ((ull*)&b0)[1];
            ull p10 = ((ull*)&b1)[0], p11 = ((ull*)&b1)[1];
#pragma unroll
            for (int i = 0; i < 4; i++) {
                float a = Ts1[kk][ty * 4 + i];
                ull a2 = pack2(a, a);
                fma2(s2[i][0], a2, p00);
                fma2(s2[i][1], a2, p01);
                fma2(s2[i][2], a2, p10);
                fma2(s2[i][3], a2, p11);
            }
        }
        __syncthreads();
    }

    // write scaled scores to P
#pragma unroll
    for (int i = 0; i < 4; i++) {
        int row = ty * 4 + i;
        float x0, x1, x2, x3, y0, y1, y2, y3;
        unpack2(s2[i][0], x0, x1); unpack2(s2[i][1], x2, x3);
        unpack2(s2[i][2], y0, y1); unpack2(s2[i][3], y2, y3);
        const float sc = 0.125f;   // 1/sqrt(HEAD_DIM=64)
        *(float4*)&P[row][tx * 4]      = make_float4(x0 * sc, x1 * sc, x2 * sc, x3 * sc);
        *(float4*)&P[row][64 + tx * 4] = make_float4(y0 * sc, y1 * sc, y2 * sc, y3 * sc);
    }
    __syncthreads();

    // ---- softmax per row (threads 0..63) ----
    if (t < 64) {
        float m = -1e30f;
#pragma unroll 4
        for (int c = 0; c < 128; c++) m = fmaxf(m, P[t][c]);
        float sum = 0.f;
#pragma unroll 4
        for (int c = 0; c < 128; c++) {
            float e = __expf(P[t][c] - m);
            P[t][c] = e;
            sum += e;
        }
        float inv = 1.f / sum;
#pragma unroll 4
        for (int c = 0; c < 128; c++) P[t][c] *= inv;
    }
    __syncthreads();

    // ---- phase 2: O = P * V, in 8 chunks of 128 output cols ----
    const int vrow = t >> 5;         // 0..7
    const int vcol = (t & 31) * 4;   // 0..124
    for (int nc = 0; nc < 8; nc++) {
        ull o2[4][4];
#pragma unroll
        for (int i = 0; i < 4; i++)
#pragma unroll
            for (int j = 0; j < 4; j++) o2[i][j] = 0ull;

        const float* Vp = v + base + (long)(s0 + vrow) * DD + nc * 128 + vcol;
        float4 vv = *(const float4*)Vp;

        for (int r0 = 0; r0 < 128; r0 += 8) {
            *(float4*)&Ts0[vrow][vcol] = vv;
            __syncthreads();
            if (r0 + 8 < 128) vv = *(const float4*)(Vp + (long)(r0 + 8) * DD);

#pragma unroll
            for (int kk = 0; kk < 8; kk++) {
                float4 b0 = *(const float4*)&Ts0[kk][tx * 4];
                float4 b1 = *(const float4*)&Ts0[kk][64 + tx * 4];
                ull p00 = ((ull*)&b0)[0], p01 = ((ull*)&b0)[1];
                ull p10 = ((ull*)&b1)[0], p11 = ((ull*)&b1)[1];
#pragma unroll
                for (int i = 0; i < 4; i++) {
                    float a = P[ty * 4 + i][r0 + kk];
                    ull a2 = pack2(a, a);
                    fma2(o2[i][0], a2, p00);
                    fma2(o2[i][1], a2, p01);
                    fma2(o2[i][2], a2, p10);
                    fma2(o2[i][3], a2, p11);
                }
            }
            __syncthreads();
        }

        // accumulate into overlap buffer
#pragma unroll
        for (int i = 0; i < 4; i++) {
            long idx = ((long)b * SS + q0 + ty * 4 + i) * DD + nc * 128;
            float x0, x1, x2, x3, y0, y1, y2, y3;
            unpack2(o2[i][0], x0, x1); unpack2(o2[i][1], x2, x3);
            unpack2(o2[i][2], y0, y1); unpack2(o2[i][3], y2, y3);
            atomicAdd(&acc[idx + tx * 4 + 0], x0);
            atomicAdd(&acc[idx + tx * 4 + 1], x1);
            atomicAdd(&acc[idx + tx * 4 + 2], x2);
            atomicAdd(&acc[idx + tx * 4 + 3], x3);
            atomicAdd(&acc[idx + 64 + tx * 4 + 0], y0);
            atomicAdd(&acc[idx + 64 + tx * 4 + 1], y1);
            atomicAdd(&acc[idx + 64 + tx * 4 + 2], y2);
            atomicAdd(&acc[idx + 64 + tx * 4 + 3], y3);
        }
    }
}

// ---------------- launch ----------------------------------------------------
extern "C" void kernel_launch(void* const* d_in, const int* in_sizes, int n_in,
                              void* d_out, int out_size)
{
    const float* x  = (const float*)d_in[0];
    const float* Wq = (const float*)d_in[1];
    const float* bq = (const float*)d_in[2];
    const float* Wk = (const float*)d_in[3];
    const float* bk = (const float*)d_in[4];
    const float* Wv = (const float*)d_in[5];
    const float* bv = (const float*)d_in[6];
    const float* Wo = (const float*)d_in[7];
    const float* bo = (const float*)d_in[8];
    float* out = (float*)d_out;

    float *gq, *gk, *gv, *gacc;
    cudaGetSymbolAddress((void**)&gq,   g_q);
    cudaGetSymbolAddress((void**)&gk,   g_k);
    cudaGetSymbolAddress((void**)&gv,   g_v);
    cudaGetSymbolAddress((void**)&gacc, g_acc);

    const int M = BB * SS, N = DD, K = DD;
    dim3 gemm_grid(N / 128, M / 128);
    dim3 blk(256);

    zero_f4<<<2048, 256>>>((float4*)gacc, BSD / 4);
    sgemm_bias<false><<<gemm_grid, blk>>>(x, Wq, bq, gq, M, N, K);
    sgemm_bias<false><<<gemm_grid, blk>>>(x, Wk, bk, gk, M, N, K);
    sgemm_bias<false><<<gemm_grid, blk>>>(x, Wv, bv, gv, M, N, K);
    window_attn<<<dim3(2 * NW, BB), blk>>>(gq, gk, gv, gacc);
    sgemm_bias<true><<<gemm_grid, blk>>>(gacc, Wo, bo, out, M, N, K);
}

// round 3
// speedup vs baseline: 1.9034x; 1.9034x over previous
#include <cuda_runtime.h>
#include <cuda_bf16.h>
#include <cstdint>
#include <math.h>

// Fixed shapes: B=4, S=4096, D=1024, WINDOW=128, stride 64
#define BB   4
#define SS   4096
#define DD   1024
#define NW   63
#define MM   (BB*SS)         // 16384
#define BSD  (BB*SS*DD)      // 16,777,216

typedef unsigned long long ull;

// ---------------- scratch (device globals; no allocation allowed) ----------
__device__ float g_q[BSD];
__device__ float g_k[BSD];
__device__ float g_v[BSD];
__device__ float g_acc[BSD];
__device__ __nv_bfloat16 g_xh[BSD];
__device__ __nv_bfloat16 g_xl[BSD];
__device__ __nv_bfloat16 g_ah[BSD];
__device__ __nv_bfloat16 g_al[BSD];
__device__ __nv_bfloat16 g_wth[4][DD*DD];   // transposed weights hi  [N,K]
__device__ __nv_bfloat16 g_wtl[4][DD*DD];   // transposed weights lo  [N,K]

// ---------------- helpers ----------------------------------------------------
__device__ __forceinline__ uint32_t smem_u32(const void* p) {
    uint32_t a;
    asm("{ .reg .u64 t; cvta.to.shared.u64 t, %1; cvt.u32.u64 %0, t; }" : "=r"(a) : "l"(p));
    return a;
}

#define SW128(off) ((off) ^ (((off) >> 3) & 0x70))

#define CP16(dst, src) \
    asm volatile("cp.async.cg.shared.global [%0], [%1], 16;" \
        :: "r"(dst), "l"(__cvta_generic_to_global(src)) : "memory")

#define LDSM_X4(r, a) \
    asm volatile("ldmatrix.sync.aligned.m8n8.x4.shared.b16 {%0,%1,%2,%3}, [%4];" \
        : "=r"((r)[0]), "=r"((r)[1]), "=r"((r)[2]), "=r"((r)[3]) : "r"(a))

#define MMA16816(c, a, b0, b1) \
    asm volatile("mma.sync.aligned.m16n8k16.row.col.f32.bf16.bf16.f32 " \
        "{%0,%1,%2,%3}, {%4,%5,%6,%7}, {%8,%9}, {%0,%1,%2,%3};" \
        : "+f"((c)[0]), "+f"((c)[1]), "+f"((c)[2]), "+f"((c)[3]) \
        : "r"((a)[0]), "r"((a)[1]), "r"((a)[2]), "r"((a)[3]), "r"(b0), "r"(b1))

// ---------------- f32x2 packed FMA (attention kernel) ----------------------
__device__ __forceinline__ ull pack2(float lo, float hi) {
    ull r; asm("mov.b64 %0, {%1,%2};" : "=l"(r) : "f"(lo), "f"(hi)); return r;
}
__device__ __forceinline__ void unpack2(ull v, float &lo, float &hi) {
    asm("mov.b64 {%0,%1}, %2;" : "=f"(lo), "=f"(hi) : "l"(v));
}
__device__ __forceinline__ void fma2(ull &c, ull a, ull b) {
    asm("fma.rn.f32x2 %0, %1, %2, %0;" : "+l"(c) : "l"(a), "l"(b));
}

// ---------------- small kernels ---------------------------------------------
__global__ void zero_f4(float4* __restrict__ p, int n4) {
    int i = blockIdx.x * blockDim.x + threadIdx.x;
    int st = gridDim.x * blockDim.x;
    float4 z = make_float4(0.f, 0.f, 0.f, 0.f);
    for (; i < n4; i += st) p[i] = z;
}

__device__ __forceinline__ uint32_t pkbf(__nv_bfloat16 a, __nv_bfloat16 b) {
    __nv_bfloat162 t = __halves2bfloat162(a, b);
    return *reinterpret_cast<uint32_t*>(&t);
}

// fp32 -> (hi, lo) bf16 split; optional count-scale per sequence row
template<bool SCALE>
__global__ void split_bf16(const float4* __restrict__ in, uint2* __restrict__ hi,
                           uint2* __restrict__ lo, int n4) {
    int i = blockIdx.x * blockDim.x + threadIdx.x;
    int st = gridDim.x * blockDim.x;
    for (; i < n4; i += st) {
        float4 v = in[i];
        if (SCALE) {
            int s = (i >> 8) & (SS - 1);
            float sc = (s < 64 || s >= SS - 64) ? 1.f : 0.5f;
            v.x *= sc; v.y *= sc; v.z *= sc; v.w *= sc;
        }
        __nv_bfloat16 h0 = __float2bfloat16(v.x), h1 = __float2bfloat16(v.y);
        __nv_bfloat16 h2 = __float2bfloat16(v.z), h3 = __float2bfloat16(v.w);
        __nv_bfloat16 l0 = __float2bfloat16(v.x - __bfloat162float(h0));
        __nv_bfloat16 l1 = __float2bfloat16(v.y - __bfloat162float(h1));
        __nv_bfloat16 l2 = __float2bfloat16(v.z - __bfloat162float(h2));
        __nv_bfloat16 l3 = __float2bfloat16(v.w - __bfloat162float(h3));
        hi[i] = make_uint2(pkbf(h0, h1), pkbf(h2, h3));
        lo[i] = make_uint2(pkbf(l0, l1), pkbf(l2, l3));
    }
}

// W[K,N] fp32 -> Wt[N,K] bf16 hi/lo
__global__ void transpose_split(const float* __restrict__ W,
                                __nv_bfloat16* __restrict__ hi,
                                __nv_bfloat16* __restrict__ lo) {
    __shared__ float tl[32][33];
    int bx = blockIdx.x * 32, by = blockIdx.y * 32;
    int tx = threadIdx.x, ty = threadIdx.y;
#pragma unroll
    for (int r = 0; r < 32; r += 8)
        tl[ty + r][tx] = W[(long)(by + ty + r) * DD + bx + tx];
    __syncthreads();
#pragma unroll
    for (int r = 0; r < 32; r += 8) {
        float v = tl[tx][ty + r];
        __nv_bfloat16 h = __float2bfloat16(v);
        long o = (long)(bx + ty + r) * DD + by + tx;
        hi[o] = h;
        lo[o] = __float2bfloat16(v - __bfloat162float(h));
    }
}

// ---------------- mma.sync split GEMM ----------------------------------------
// C[16384,1024] = (Ah+Al)[M,K] * (Bh+Bl)^T[N,K] + bias, 3 accumulating passes.
// CTA tile 128x128, warp tile 64x32, K-chunk 64 bf16, double-buffered cp.async.
#define GEMM_SMEM 65536

__global__ void __launch_bounds__(256, 2) gemm_mma(
    const __nv_bfloat16* __restrict__ Ah, const __nv_bfloat16* __restrict__ Al,
    const __nv_bfloat16* __restrict__ Bh, const __nv_bfloat16* __restrict__ Bl,
    const float* __restrict__ bias, float* __restrict__ C)
{
    extern __shared__ char smem[];
    const uint32_t sb = smem_u32(smem);
    const int t = threadIdx.x;
    const int lane = t & 31, wid = t >> 5;
    const int wrow = wid & 1;          // 2 row groups of 64
    const int wcol = wid >> 1;         // 4 col groups of 32
    const long m0 = (long)blockIdx.y * 128;
    const int  n0 = blockIdx.x * 128;

    const uint32_t sA[2] = { sb,         sb + 16384 };
    const uint32_t sB[2] = { sb + 32768, sb + 49152 };

    // cp.async per-thread targets (4 x 16B for A, 4 for B per chunk)
    int rowg[4]; uint32_t dsts[4];
#pragma unroll
    for (int i = 0; i < 4; i++) {
        int u = t + 256 * i;
        rowg[i] = u >> 3;
        dsts[i] = SW128((u >> 3) * 128 + (u & 7) * 16);
    }
    const int kcol8 = (t & 7) * 8;     // bf16 offset within chunk

    const __nv_bfloat16* APass[3] = {Ah, Ah, Al};
    const __nv_bfloat16* BPass[3] = {Bh, Bl, Bh};

    // ldmatrix address components (chunk-invariant)
    uint32_t a_rowoff[4], a_swz[4];
#pragma unroll
    for (int ms = 0; ms < 4; ms++) {
        int row = wrow * 64 + ms * 16 + (lane & 15);
        a_rowoff[ms] = row * 128;
        a_swz[ms]    = (row & 7) * 16;
    }
    const uint32_t a_kext = (lane >> 4) * 16;
    uint32_t b_rowoff[2], b_swz[2];
#pragma unroll
    for (int np = 0; np < 2; np++) {
        int row = wcol * 32 + np * 16 + ((lane >> 4) & 1) * 8 + (lane & 7);
        b_rowoff[np] = row * 128;
        b_swz[np]    = (row & 7) * 16;
    }
    const uint32_t b_kext = ((lane >> 3) & 1) * 16;

    float acc[4][4][4];
#pragma unroll
    for (int i = 0; i < 4; i++)
#pragma unroll
        for (int j = 0; j < 4; j++)
#pragma unroll
            for (int r = 0; r < 4; r++) acc[i][j][r] = 0.f;

    auto load_chunk = [&](int c, int buf) {
        int pass = c >> 4, kc = (c & 15) * 64;
        const __nv_bfloat16* Ab = APass[pass] + kc + kcol8;
        const __nv_bfloat16* Bb = BPass[pass] + kc + kcol8;
#pragma unroll
        for (int i = 0; i < 4; i++) CP16(sA[buf] + dsts[i], Ab + (m0 + rowg[i]) * DD);
#pragma unroll
        for (int i = 0; i < 4; i++) CP16(sB[buf] + dsts[i], Bb + (long)(n0 + rowg[i]) * DD);
        asm volatile("cp.async.commit_group;" ::: "memory");
    };

    load_chunk(0, 0);

    for (int c = 0; c < 48; c++) {
        const int buf = c & 1;
        if (c + 1 < 48) {
            load_chunk(c + 1, buf ^ 1);
            asm volatile("cp.async.wait_group 1;" ::: "memory");
        } else {
            asm volatile("cp.async.wait_group 0;" ::: "memory");
        }
        __syncthreads();

        const uint32_t bA = sA[buf], bB = sB[buf];
#pragma unroll
        for (int k16 = 0; k16 < 4; k16++) {
            const uint32_t kb = k16 * 32;
            uint32_t afr[4][4], bfr[2][4];
#pragma unroll
            for (int ms = 0; ms < 4; ms++)
                LDSM_X4(afr[ms], bA + a_rowoff[ms] + ((kb + a_kext) ^ a_swz[ms]));
#pragma unroll
            for (int np = 0; np < 2; np++)
                LDSM_X4(bfr[np], bB + b_rowoff[np] + ((kb + b_kext) ^ b_swz[np]));
#pragma unroll
            for (int ms = 0; ms < 4; ms++)
#pragma unroll
                for (int ns = 0; ns < 4; ns++)
                    MMA16816(acc[ms][ns], afr[ms],
                             bfr[ns >> 1][(ns & 1) * 2], bfr[ns >> 1][(ns & 1) * 2 + 1]);
        }
        __syncthreads();
    }

    // epilogue: direct reg -> global with bias
#pragma unroll
    for (int ms = 0; ms < 4; ms++) {
        long r0 = m0 + wrow * 64 + ms * 16 + (lane >> 2);
#pragma unroll
        for (int ns = 0; ns < 4; ns++) {
            int col = n0 + wcol * 32 + ns * 8 + (lane & 3) * 2;
            float2 bv = *(const float2*)(bias + col);
            float2 o0 = make_float2(acc[ms][ns][0] + bv.x, acc[ms][ns][1] + bv.y);
            float2 o1 = make_float2(acc[ms][ns][2] + bv.x, acc[ms][ns][3] + bv.y);
            *(float2*)(C + r0 * DD + col)       = o0;
            *(float2*)(C + (r0 + 8) * DD + col) = o1;
        }
    }
}

// ---------------- windowed attention (fp32 f32x2, unchanged) -----------------
__global__ void __launch_bounds__(256) window_attn(
    const float* __restrict__ q, const float* __restrict__ k,
    const float* __restrict__ v, float* __restrict__ acc)
{
    __shared__ float P[64][132];
    __shared__ float Ts0[8][128];
    __shared__ float Ts1[8][64];

    const int t  = threadIdx.x;
    const int tx = t & 15;
    const int ty = t >> 4;
    const int w  = blockIdx.x >> 1;
    const int qh = blockIdx.x & 1;
    const int b  = blockIdx.y;
    const long base = (long)b * SS * DD;
    const int s0 = w * 64;
    const int q0 = s0 + qh * 64;

    const int lrow = t >> 1;
    const int lcol = (t & 1) * 4;
    const float* Qp = q + base + (long)(q0 + lrow) * DD + lcol;
    const float* Kp = k + base + (long)(s0 + lrow) * DD + lcol;

    float4 kv = *(const float4*)Kp;
    float4 qv = make_float4(0, 0, 0, 0);
    if (t < 128) qv = *(const float4*)Qp;

    ull s2[4][4];
#pragma unroll
    for (int i = 0; i < 4; i++)
#pragma unroll
        for (int j = 0; j < 4; j++) s2[i][j] = 0ull;

    for (int k0 = 0; k0 < DD; k0 += 8) {
        if (t < 128) {
            Ts1[lcol + 0][lrow] = qv.x; Ts1[lcol + 1][lrow] = qv.y;
            Ts1[lcol + 2][lrow] = qv.z; Ts1[lcol + 3][lrow] = qv.w;
        }
        Ts0[lcol + 0][lrow] = kv.x; Ts0[lcol + 1][lrow] = kv.y;
        Ts0[lcol + 2][lrow] = kv.z; Ts0[lcol + 3][lrow] = kv.w;
        __syncthreads();

        if (k0 + 8 < DD) {
            kv = *(const float4*)(Kp + k0 + 8);
            if (t < 128) qv = *(const float4*)(Qp + k0 + 8);
        }

#pragma unroll
        for (int kk = 0; kk < 8; kk++) {
            float4 b0 = *(const float4*)&Ts0[kk][tx * 4];
            float4 b1 = *(const float4*)&Ts0[kk][64 + tx * 4];
            ull p00 = ((ull*)&b0)[0], p01 = ((ull*)&b0)[1];
            ull p10 = ((ull*)&b1)[0], p11 = ((ull*)&b1)[1];
#pragma unroll
            for (int i = 0; i < 4; i++) {
                float a = Ts1[kk][ty * 4 + i];
                ull a2 = pack2(a, a);
                fma2(s2[i][0], a2, p00);
                fma2(s2[i][1], a2, p01);
                fma2(s2[i][2], a2, p10);
                fma2(s2[i][3], a2, p11);
            }
        }
        __syncthreads();
    }

#pragma unroll
    for (int i = 0; i < 4; i++) {
        int row = ty * 4 + i;
        float x0, x1, x2, x3, y0, y1, y2, y3;
        unpack2(s2[i][0], x0, x1); unpack2(s2[i][1], x2, x3);
        unpack2(s2[i][2], y0, y1); unpack2(s2[i][3], y2, y3);
        const float sc = 0.125f;
        *(float4*)&P[row][tx * 4]      = make_float4(x0 * sc, x1 * sc, x2 * sc, x3 * sc);
        *(float4*)&P[row][64 + tx * 4] = make_float4(y0 * sc, y1 * sc, y2 * sc, y3 * sc);
    }
    __syncthreads();

    if (t < 64) {
        float m = -1e30f;
#pragma unroll 4
        for (int c = 0; c < 128; c++) m = fmaxf(m, P[t][c]);
        float sum = 0.f;
#pragma unroll 4
        for (int c = 0; c < 128; c++) {
            float e = __expf(P[t][c] - m);
            P[t][c] = e;
            sum += e;
        }
        float inv = 1.f / sum;
#pragma unroll 4
        for (int c = 0; c < 128; c++) P[t][c] *= inv;
    }
    __syncthreads();

    const int vrow = t >> 5;
    const int vcol = (t & 31) * 4;
    for (int nc = 0; nc < 8; nc++) {
        ull o2[4][4];
#pragma unroll
        for (int i = 0; i < 4; i++)
#pragma unroll
            for (int j = 0; j < 4; j++) o2[i][j] = 0ull;

        const float* Vp = v + base + (long)(s0 + vrow) * DD + nc * 128 + vcol;
        float4 vv = *(const float4*)Vp;

        for (int r0 = 0; r0 < 128; r0 += 8) {
            *(float4*)&Ts0[vrow][vcol] = vv;
            __syncthreads();
            if (r0 + 8 < 128) vv = *(const float4*)(Vp + (long)(r0 + 8) * DD);

#pragma unroll
            for (int kk = 0; kk < 8; kk++) {
                float4 b0 = *(const float4*)&Ts0[kk][tx * 4];
                float4 b1 = *(const float4*)&Ts0[kk][64 + tx * 4];
                ull p00 = ((ull*)&b0)[0], p01 = ((ull*)&b0)[1];
                ull p10 = ((ull*)&b1)[0], p11 = ((ull*)&b1)[1];
#pragma unroll
                for (int i = 0; i < 4; i++) {
                    float a = P[ty * 4 + i][r0 + kk];
                    ull a2 = pack2(a, a);
                    fma2(o2[i][0], a2, p00);
                    fma2(o2[i][1], a2, p01);
                    fma2(o2[i][2], a2, p10);
                    fma2(o2[i][3], a2, p11);
                }
            }
            __syncthreads();
        }

#pragma unroll
        for (int i = 0; i < 4; i++) {
            long idx = ((long)b * SS + q0 + ty * 4 + i) * DD + nc * 128;
            float x0, x1, x2, x3, y0, y1, y2, y3;
            unpack2(o2[i][0], x0, x1); unpack2(o2[i][1], x2, x3);
            unpack2(o2[i][2], y0, y1); unpack2(o2[i][3], y2, y3);
            atomicAdd(&acc[idx + tx * 4 + 0], x0);
            atomicAdd(&acc[idx + tx * 4 + 1], x1);
            atomicAdd(&acc[idx + tx * 4 + 2], x2);
            atomicAdd(&acc[idx + tx * 4 + 3], x3);
            atomicAdd(&acc[idx + 64 + tx * 4 + 0], y0);
            atomicAdd(&acc[idx + 64 + tx * 4 + 1], y1);
            atomicAdd(&acc[idx + 64 + tx * 4 + 2], y2);
            atomicAdd(&acc[idx + 64 + tx * 4 + 3], y3);
        }
    }
}

// ---------------- launch -----------------------------------------------------
extern "C" void kernel_launch(void* const* d_in, const int* in_sizes, int n_in,
                              void* d_out, int out_size)
{
    const float* x  = (const float*)d_in[0];
    const float* Wq = (const float*)d_in[1];
    const float* bq = (const float*)d_in[2];
    const float* Wk = (const float*)d_in[3];
    const float* bk = (const float*)d_in[4];
    const float* Wv = (const float*)d_in[5];
    const float* bv = (const float*)d_in[6];
    const float* Wo = (const float*)d_in[7];
    const float* bo = (const float*)d_in[8];
    float* out = (float*)d_out;

    float *gq, *gk, *gv, *gacc;
    __nv_bfloat16 *xh, *xl, *ah, *al, *wth, *wtl;
    cudaGetSymbolAddress((void**)&gq,   g_q);
    cudaGetSymbolAddress((void**)&gk,   g_k);
    cudaGetSymbolAddress((void**)&gv,   g_v);
    cudaGetSymbolAddress((void**)&gacc, g_acc);
    cudaGetSymbolAddress((void**)&xh,   g_xh);
    cudaGetSymbolAddress((void**)&xl,   g_xl);
    cudaGetSymbolAddress((void**)&ah,   g_ah);
    cudaGetSymbolAddress((void**)&al,   g_al);
    cudaGetSymbolAddress((void**)&wth,  g_wth);
    cudaGetSymbolAddress((void**)&wtl,  g_wtl);

    cudaFuncSetAttribute(gemm_mma, cudaFuncAttributeMaxDynamicSharedMemorySize, GEMM_SMEM);

    dim3 tb(32, 8);
    dim3 tg(32, 32);
    const float* Ws[4] = {Wq, Wk, Wv, Wo};
    for (int i = 0; i < 4; i++)
        transpose_split<<<tg, tb>>>(Ws[i], wth + (long)i * DD * DD, wtl + (long)i * DD * DD);

    split_bf16<false><<<2048, 256>>>((const float4*)x, (uint2*)xh, (uint2*)xl, BSD / 4);
    zero_f4<<<2048, 256>>>((float4*)gacc, BSD / 4);

    dim3 ggrid(DD / 128, MM / 128);   // (8, 128)
    gemm_mma<<<ggrid, 256, GEMM_SMEM>>>(xh, xl, wth + 0L * DD * DD, wtl + 0L * DD * DD, bq, gq);
    gemm_mma<<<ggrid, 256, GEMM_SMEM>>>(xh, xl, wth + 1L * DD * DD, wtl + 1L * DD * DD, bk, gk);
    gemm_mma<<<ggrid, 256, GEMM_SMEM>>>(xh, xl, wth + 2L * DD * DD, wtl + 2L * DD * DD, bv, gv);

    window_attn<<<dim3(2 * NW, BB), 256>>>(gq, gk, gv, gacc);

    split_bf16<true><<<2048, 256>>>((const float4*)gacc, (uint2*)ah, (uint2*)al, BSD / 4);
    gemm_mma<<<ggrid, 256, GEMM_SMEM>>>(ah, al, wth + 3L * DD * DD, wtl + 3L * DD * DD, bo, out);
}

// round 4
// speedup vs baseline: 2.4125x; 1.2675x over previous
#include <cuda_runtime.h>
#include <cuda_bf16.h>
#include <cstdint>
#include <math.h>

// Fixed shapes: B=4, S=4096, D=1024, WINDOW=128, stride 64
#define BB   4
#define SS   4096
#define DD   1024
#define NW   63
#define MM   (BB*SS)         // 16384
#define BSD  (BB*SS*DD)      // 16,777,216

typedef unsigned long long ull;
typedef __nv_bfloat16 bf16;

// ---------------- scratch (device globals; no allocation allowed) ----------
__device__ bf16 g_qh[BSD]; __device__ bf16 g_ql[BSD];
__device__ bf16 g_kh[BSD]; __device__ bf16 g_kl[BSD];
__device__ bf16 g_vh[BSD]; __device__ bf16 g_vl[BSD];
__device__ bf16 g_xh[BSD]; __device__ bf16 g_xl[BSD];
__device__ bf16 g_ah[BSD]; __device__ bf16 g_al[BSD];
__device__ bf16 g_wth[4][DD*DD];
__device__ bf16 g_wtl[4][DD*DD];
__device__ float g_E[BSD];
__device__ float g_O[BSD];

// ---------------- helpers ----------------------------------------------------
__device__ __forceinline__ uint32_t smem_u32(const void* p) {
    uint32_t a;
    asm("{ .reg .u64 t; cvta.to.shared.u64 t, %1; cvt.u32.u64 %0, t; }" : "=r"(a) : "l"(p));
    return a;
}
__device__ __forceinline__ float ex2(float x) {
    float y; asm("ex2.approx.f32 %0, %1;" : "=f"(y) : "f"(x)); return y;
}

#define SW128(off) ((off) ^ (((off) >> 3) & 0x70))

#define CP16(dst, src) \
    asm volatile("cp.async.cg.shared.global [%0], [%1], 16;" \
        :: "r"(dst), "l"(__cvta_generic_to_global(src)) : "memory")

#define LDSM_X4(r, a) \
    asm volatile("ldmatrix.sync.aligned.m8n8.x4.shared.b16 {%0,%1,%2,%3}, [%4];" \
        : "=r"((r)[0]), "=r"((r)[1]), "=r"((r)[2]), "=r"((r)[3]) : "r"(a))

#define LDSM_X4T(r, a) \
    asm volatile("ldmatrix.sync.aligned.m8n8.x4.trans.shared.b16 {%0,%1,%2,%3}, [%4];" \
        : "=r"((r)[0]), "=r"((r)[1]), "=r"((r)[2]), "=r"((r)[3]) : "r"(a))

#define MMA16816(c, a, b0, b1) \
    asm volatile("mma.sync.aligned.m16n8k16.row.col.f32.bf16.bf16.f32 " \
        "{%0,%1,%2,%3}, {%4,%5,%6,%7}, {%8,%9}, {%0,%1,%2,%3};" \
        : "+f"((c)[0]), "+f"((c)[1]), "+f"((c)[2]), "+f"((c)[3]) \
        : "r"((a)[0]), "r"((a)[1]), "r"((a)[2]), "r"((a)[3]), "r"(b0), "r"(b1))

__device__ __forceinline__ uint32_t pkbf(bf16 a, bf16 b) {
    __nv_bfloat162 t = __halves2bfloat162(a, b);
    return *reinterpret_cast<uint32_t*>(&t);
}
__device__ __forceinline__ void split1(float v, bf16 &h, bf16 &l) {
    h = __float2bfloat16(v);
    l = __float2bfloat16(v - __bfloat162float(h));
}

// ---------------- small kernels ---------------------------------------------
__global__ void zero_f4(float4* __restrict__ p, int n4) {
    int i = blockIdx.x * blockDim.x + threadIdx.x;
    int st = gridDim.x * blockDim.x;
    float4 z = make_float4(0.f, 0.f, 0.f, 0.f);
    for (; i < n4; i += st) p[i] = z;
}

__global__ void split_x(const float4* __restrict__ in, uint2* __restrict__ hi,
                        uint2* __restrict__ lo, int n4) {
    int i = blockIdx.x * blockDim.x + threadIdx.x;
    int st = gridDim.x * blockDim.x;
    for (; i < n4; i += st) {
        float4 v = in[i];
        bf16 h0,h1,h2,h3,l0,l1,l2,l3;
        split1(v.x,h0,l0); split1(v.y,h1,l1); split1(v.z,h2,l2); split1(v.w,h3,l3);
        hi[i] = make_uint2(pkbf(h0,h1), pkbf(h2,h3));
        lo[i] = make_uint2(pkbf(l0,l1), pkbf(l2,l3));
    }
}

// final = (E + O) * countscale, split to bf16 hi/lo
__global__ void combine_split(const float4* __restrict__ E, const float4* __restrict__ O,
                              uint2* __restrict__ hi, uint2* __restrict__ lo, int n4) {
    int i = blockIdx.x * blockDim.x + threadIdx.x;
    int st = gridDim.x * blockDim.x;
    for (; i < n4; i += st) {
        float4 e = E[i], o = O[i];
        int s = (i >> 8) & (SS - 1);
        float sc = (s < 64 || s >= SS - 64) ? 1.f : 0.5f;
        float4 v = make_float4((e.x+o.x)*sc, (e.y+o.y)*sc, (e.z+o.z)*sc, (e.w+o.w)*sc);
        bf16 h0,h1,h2,h3,l0,l1,l2,l3;
        split1(v.x,h0,l0); split1(v.y,h1,l1); split1(v.z,h2,l2); split1(v.w,h3,l3);
        hi[i] = make_uint2(pkbf(h0,h1), pkbf(h2,h3));
        lo[i] = make_uint2(pkbf(l0,l1), pkbf(l2,l3));
    }
}

// W[K,N] fp32 -> Wt[N,K] bf16 hi/lo
__global__ void transpose_split(const float* __restrict__ W,
                                bf16* __restrict__ hi, bf16* __restrict__ lo) {
    __shared__ float tl[32][33];
    int bx = blockIdx.x * 32, by = blockIdx.y * 32;
    int tx = threadIdx.x, ty = threadIdx.y;
#pragma unroll
    for (int r = 0; r < 32; r += 8)
        tl[ty + r][tx] = W[(long)(by + ty + r) * DD + bx + tx];
    __syncthreads();
#pragma unroll
    for (int r = 0; r < 32; r += 8) {
        float v = tl[tx][ty + r];
        bf16 h, l; split1(v, h, l);
        long o = (long)(bx + ty + r) * DD + by + tx;
        hi[o] = h; lo[o] = l;
    }
}

// ---------------- mma.sync split GEMM ----------------------------------------
// OMODE 0: fp32 out + bias.  OMODE 1: bf16 hi/lo out + bias.
#define GEMM_SMEM 65536

template<int OMODE>
__global__ void __launch_bounds__(256, 2) gemm_mma(
    const bf16* __restrict__ Ah, const bf16* __restrict__ Al,
    const bf16* __restrict__ Bh, const bf16* __restrict__ Bl,
    const float* __restrict__ bias, float* __restrict__ C,
    bf16* __restrict__ Chi, bf16* __restrict__ Clo)
{
    extern __shared__ char smem[];
    const uint32_t sb = smem_u32(smem);
    const int t = threadIdx.x;
    const int lane = t & 31, wid = t >> 5;
    const int wrow = wid & 1;
    const int wcol = wid >> 1;
    const long m0 = (long)blockIdx.y * 128;
    const int  n0 = blockIdx.x * 128;

    const uint32_t sA[2] = { sb,         sb + 16384 };
    const uint32_t sB[2] = { sb + 32768, sb + 49152 };

    int rowg[4]; uint32_t dsts[4];
#pragma unroll
    for (int i = 0; i < 4; i++) {
        int u = t + 256 * i;
        rowg[i] = u >> 3;
        dsts[i] = SW128((u >> 3) * 128 + (u & 7) * 16);
    }
    const int kcol8 = (t & 7) * 8;

    const bf16* APass[3] = {Ah, Ah, Al};
    const bf16* BPass[3] = {Bh, Bl, Bh};

    uint32_t a_rowoff[4], a_swz[4];
#pragma unroll
    for (int ms = 0; ms < 4; ms++) {
        int row = wrow * 64 + ms * 16 + (lane & 15);
        a_rowoff[ms] = row * 128;
        a_swz[ms]    = (row & 7) * 16;
    }
    const uint32_t a_kext = (lane >> 4) * 16;
    uint32_t b_rowoff[2], b_swz[2];
#pragma unroll
    for (int np = 0; np < 2; np++) {
        int row = wcol * 32 + np * 16 + ((lane >> 4) & 1) * 8 + (lane & 7);
        b_rowoff[np] = row * 128;
        b_swz[np]    = (row & 7) * 16;
    }
    const uint32_t b_kext = ((lane >> 3) & 1) * 16;

    float acc[4][4][4];
#pragma unroll
    for (int i = 0; i < 4; i++)
#pragma unroll
        for (int j = 0; j < 4; j++)
#pragma unroll
            for (int r = 0; r < 4; r++) acc[i][j][r] = 0.f;

    auto load_chunk = [&](int c, int buf) {
        int pass = c >> 4, kc = (c & 15) * 64;
        const bf16* Ab = APass[pass] + kc + kcol8;
        const bf16* Bb = BPass[pass] + kc + kcol8;
#pragma unroll
        for (int i = 0; i < 4; i++) CP16(sA[buf] + dsts[i], Ab + (m0 + rowg[i]) * DD);
#pragma unroll
        for (int i = 0; i < 4; i++) CP16(sB[buf] + dsts[i], Bb + (long)(n0 + rowg[i]) * DD);
        asm volatile("cp.async.commit_group;" ::: "memory");
    };

    load_chunk(0, 0);

    for (int c = 0; c < 48; c++) {
        const int buf = c & 1;
        if (c + 1 < 48) {
            load_chunk(c + 1, buf ^ 1);
            asm volatile("cp.async.wait_group 1;" ::: "memory");
        } else {
            asm volatile("cp.async.wait_group 0;" ::: "memory");
        }
        __syncthreads();

        const uint32_t bA = sA[buf], bB = sB[buf];
#pragma unroll
        for (int k16 = 0; k16 < 4; k16++) {
            const uint32_t kb = k16 * 32;
            uint32_t afr[4][4], bfr[2][4];
#pragma unroll
            for (int ms = 0; ms < 4; ms++)
                LDSM_X4(afr[ms], bA + a_rowoff[ms] + ((kb + a_kext) ^ a_swz[ms]));
#pragma unroll
            for (int np = 0; np < 2; np++)
                LDSM_X4(bfr[np], bB + b_rowoff[np] + ((kb + b_kext) ^ b_swz[np]));
#pragma unroll
            for (int ms = 0; ms < 4; ms++)
#pragma unroll
                for (int ns = 0; ns < 4; ns++)
                    MMA16816(acc[ms][ns], afr[ms],
                             bfr[ns >> 1][(ns & 1) * 2], bfr[ns >> 1][(ns & 1) * 2 + 1]);
        }
        __syncthreads();
    }

#pragma unroll
    for (int ms = 0; ms < 4; ms++) {
        long r0 = m0 + wrow * 64 + ms * 16 + (lane >> 2);
#pragma unroll
        for (int ns = 0; ns < 4; ns++) {
            int col = n0 + wcol * 32 + ns * 8 + (lane & 3) * 2;
            float2 bv = *(const float2*)(bias + col);
            float v00 = acc[ms][ns][0] + bv.x, v01 = acc[ms][ns][1] + bv.y;
            float v10 = acc[ms][ns][2] + bv.x, v11 = acc[ms][ns][3] + bv.y;
            if (OMODE == 0) {
                *(float2*)(C + r0 * DD + col)       = make_float2(v00, v01);
                *(float2*)(C + (r0 + 8) * DD + col) = make_float2(v10, v11);
            } else {
                bf16 h0,h1,l0,l1;
                split1(v00, h0, l0); split1(v01, h1, l1);
                *(uint32_t*)(Chi + r0 * DD + col) = pkbf(h0, h1);
                *(uint32_t*)(Clo + r0 * DD + col) = pkbf(l0, l1);
                split1(v10, h0, l0); split1(v11, h1, l1);
                *(uint32_t*)(Chi + (r0 + 8) * DD + col) = pkbf(h0, h1);
                *(uint32_t*)(Clo + (r0 + 8) * DD + col) = pkbf(l0, l1);
            }
        }
    }
}

// ---------------- windowed attention via mma.sync ----------------------------
// One CTA per (window, batch): 128 queries x 128 keys over d=1024.
// Phase1: S = Q*K^T (3-pass split)  ->  softmax (no max-sub; scores small)
// Phase2: O = P*V (3-pass: Ph*Vh + Ph*Vl + Pl*Vh), 16 n-chunks of 64 cols.
#define ATT_PHI   65536
#define ATT_PLO   98304
#define ATT_RED   131072
#define ATT_SMEM  133632

__global__ void __launch_bounds__(256, 1) window_attn_mma(
    const bf16* __restrict__ qh, const bf16* __restrict__ ql,
    const bf16* __restrict__ kh, const bf16* __restrict__ kl,
    const bf16* __restrict__ vh, const bf16* __restrict__ vl,
    float* __restrict__ Ebuf, float* __restrict__ Obuf)
{
    extern __shared__ char smem[];
    const uint32_t sb = smem_u32(smem);
    const int t = threadIdx.x;
    const int lane = t & 31, wid = t >> 5;
    const int wrow = wid & 1;
    const int wcol = wid >> 1;
    const int w = blockIdx.x, b = blockIdx.y;
    const long qbase = ((long)b * SS + w * 64) * DD;

    const uint32_t sA[2] = { sb,         sb + 16384 };
    const uint32_t sB[2] = { sb + 32768, sb + 49152 };
    const uint32_t vhb[2] = { sb,         sb + 32768 };
    const uint32_t vlb[2] = { sb + 16384, sb + 49152 };

    int rowg[4]; uint32_t dsts[4];
#pragma unroll
    for (int i = 0; i < 4; i++) {
        int u = t + 256 * i;
        rowg[i] = u >> 3;
        dsts[i] = SW128((u >> 3) * 128 + (u & 7) * 16);
    }
    const int kcol8 = (t & 7) * 8;

    uint32_t a_rowoff[4], a_swz[4];
#pragma unroll
    for (int ms = 0; ms < 4; ms++) {
        int row = wrow * 64 + ms * 16 + (lane & 15);
        a_rowoff[ms] = row * 128;
        a_swz[ms]    = (row & 7) * 16;
    }
    const uint32_t a_kext = (lane >> 4) * 16;
    uint32_t b_rowoff[2], b_swz[2];
#pragma unroll
    for (int np = 0; np < 2; np++) {
        int row = wcol * 32 + np * 16 + ((lane >> 4) & 1) * 8 + (lane & 7);
        b_rowoff[np] = row * 128;
        b_swz[np]    = (row & 7) * 16;
    }
    const uint32_t b_kext = ((lane >> 3) & 1) * 16;

    const bf16* QP[3] = {qh, qh, ql};
    const bf16* KP[3] = {kh, kl, kh};

    float acc[4][4][4];
#pragma unroll
    for (int i = 0; i < 4; i++)
#pragma unroll
        for (int j = 0; j < 4; j++)
#pragma unroll
            for (int r = 0; r < 4; r++) acc[i][j][r] = 0.f;

    auto load_qk = [&](int c, int buf) {
        int pass = c >> 4, kc = (c & 15) * 64;
        const bf16* Ab = QP[pass] + qbase + kc + kcol8;
        const bf16* Bb = KP[pass] + qbase + kc + kcol8;
#pragma unroll
        for (int i = 0; i < 4; i++) CP16(sA[buf] + dsts[i], Ab + (long)rowg[i] * DD);
#pragma unroll
        for (int i = 0; i < 4; i++) CP16(sB[buf] + dsts[i], Bb + (long)rowg[i] * DD);
        asm volatile("cp.async.commit_group;" ::: "memory");
    };

    load_qk(0, 0);

    for (int c = 0; c < 48; c++) {
        const int buf = c & 1;
        if (c + 1 < 48) {
            load_qk(c + 1, buf ^ 1);
            asm volatile("cp.async.wait_group 1;" ::: "memory");
        } else {
            asm volatile("cp.async.wait_group 0;" ::: "memory");
        }
        __syncthreads();

        const uint32_t bA = sA[buf], bB = sB[buf];
#pragma unroll
        for (int k16 = 0; k16 < 4; k16++) {
            const uint32_t kb = k16 * 32;
            uint32_t afr[4][4], bfr[2][4];
#pragma unroll
            for (int ms = 0; ms < 4; ms++)
                LDSM_X4(afr[ms], bA + a_rowoff[ms] + ((kb + a_kext) ^ a_swz[ms]));
#pragma unroll
            for (int np = 0; np < 2; np++)
                LDSM_X4(bfr[np], bB + b_rowoff[np] + ((kb + b_kext) ^ b_swz[np]));
#pragma unroll
            for (int ms = 0; ms < 4; ms++)
#pragma unroll
                for (int ns = 0; ns < 4; ns++)
                    MMA16816(acc[ms][ns], afr[ms],
                             bfr[ns >> 1][(ns & 1) * 2], bfr[ns >> 1][(ns & 1) * 2 + 1]);
        }
        __syncthreads();
    }

    // prefetch V chunk 0 while doing softmax
    auto load_v = [&](int nc, int buf) {
        const bf16* Vh = vh + qbase + nc * 64 + kcol8;
        const bf16* Vl = vl + qbase + nc * 64 + kcol8;
#pragma unroll
        for (int i = 0; i < 4; i++) CP16(vhb[buf] + dsts[i], Vh + (long)rowg[i] * DD);
#pragma unroll
        for (int i = 0; i < 4; i++) CP16(vlb[buf] + dsts[i], Vl + (long)rowg[i] * DD);
        asm volatile("cp.async.commit_group;" ::: "memory");
    };
    load_v(0, 0);

    // ---- softmax: e = exp2(score * 0.125*log2e); row sums across 4 warp cols
    const float CEXP = 0.1803368801f;
    float* red = (float*)(smem + ATT_RED);   // [4][128]
    float ps[4][2];
#pragma unroll
    for (int ms = 0; ms < 4; ms++) {
        ps[ms][0] = 0.f; ps[ms][1] = 0.f;
#pragma unroll
        for (int ns = 0; ns < 4; ns++) {
#pragma unroll
            for (int r = 0; r < 4; r++) {
                float e = ex2(acc[ms][ns][r] * CEXP);
                acc[ms][ns][r] = e;
                ps[ms][r >> 1] += e;
            }
        }
    }
#pragma unroll
    for (int off = 1; off < 4; off <<= 1)
#pragma unroll
        for (int ms = 0; ms < 4; ms++) {
            ps[ms][0] += __shfl_xor_sync(0xffffffffu, ps[ms][0], off);
            ps[ms][1] += __shfl_xor_sync(0xffffffffu, ps[ms][1], off);
        }
    if ((lane & 3) == 0) {
#pragma unroll
        for (int ms = 0; ms < 4; ms++) {
#pragma unroll
            for (int h = 0; h < 2; h++) {
                int row = wrow * 64 + ms * 16 + (lane >> 2) + h * 8;
                red[wcol * 128 + row] = ps[ms][h];
            }
        }
    }
    __syncthreads();

    // normalize + store P (bf16 hi/lo) into SW128 chunked layout
#pragma unroll
    for (int ms = 0; ms < 4; ms++) {
#pragma unroll
        for (int h = 0; h < 2; h++) {
            int row = wrow * 64 + ms * 16 + (lane >> 2) + h * 8;
            float s = red[row] + red[128 + row] + red[256 + row] + red[384 + row];
            float inv = 1.f / s;
#pragma unroll
            for (int ns = 0; ns < 4; ns++) {
                int col = wcol * 32 + ns * 8 + (lane & 3) * 2;
                float p0 = acc[ms][ns][h * 2]     * inv;
                float p1 = acc[ms][ns][h * 2 + 1] * inv;
                bf16 h0, l0, h1, l1;
                split1(p0, h0, l0); split1(p1, h1, l1);
                uint32_t off = (col >> 6) * 16384 + SW128(row * 128 + (col & 63) * 2);
                *(uint32_t*)(smem + ATT_PHI + off) = pkbf(h0, h1);
                *(uint32_t*)(smem + ATT_PLO + off) = pkbf(l0, l1);
            }
        }
    }
    __syncthreads();

    // ---- phase 2: O = P * V over 16 n-chunks of 64 cols
    // B-fragment addressing (trans ldmatrix from row-major V tile)
    const int r0v = (lane & 7) + ((lane >> 3) & 1) * 8;    // 0..15
    const uint32_t b2_row = (uint32_t)r0v * 128;
    const uint32_t b2_cs  = ((wcol * 16 + (lane >> 4) * 8) * 2) ^ ((r0v & 7) * 16);

    float* dst = (w & 1) ? Obuf : Ebuf;
    const long rowbase = (long)b * SS + w * 64 + wrow * 64;

    for (int nc = 0; nc < 16; nc++) {
        const int buf = nc & 1;
        if (nc + 1 < 16) {
            load_v(nc + 1, buf ^ 1);
            asm volatile("cp.async.wait_group 1;" ::: "memory");
        } else {
            asm volatile("cp.async.wait_group 0;" ::: "memory");
        }
        __syncthreads();

        float acc2[4][2][4];
#pragma unroll
        for (int i = 0; i < 4; i++)
#pragma unroll
            for (int j = 0; j < 2; j++)
#pragma unroll
                for (int r = 0; r < 4; r++) acc2[i][j][r] = 0.f;

#pragma unroll
        for (int pass = 0; pass < 3; pass++) {
            const uint32_t Pb = sb + ((pass < 2) ? ATT_PHI : ATT_PLO);
            const uint32_t Vb = (pass == 1) ? vlb[buf] : vhb[buf];
#pragma unroll
            for (int k16 = 0; k16 < 8; k16++) {
                const uint32_t pchunk = (k16 >> 2) * 16384;
                const uint32_t kb = (k16 & 3) * 32;
                uint32_t afr[4][4], bfr[4];
#pragma unroll
                for (int ms = 0; ms < 4; ms++)
                    LDSM_X4(afr[ms], Pb + pchunk + a_rowoff[ms] + ((kb + a_kext) ^ a_swz[ms]));
                LDSM_X4T(bfr, Vb + b2_row + (uint32_t)k16 * 2048 + b2_cs);
#pragma unroll
                for (int ms = 0; ms < 4; ms++) {
                    MMA16816(acc2[ms][0], afr[ms], bfr[0], bfr[1]);
                    MMA16816(acc2[ms][1], afr[ms], bfr[2], bfr[3]);
                }
            }
        }

        // store this 128x64 output tile
#pragma unroll
        for (int ms = 0; ms < 4; ms++) {
#pragma unroll
            for (int h = 0; h < 2; h++) {
                long s = rowbase + ms * 16 + (lane >> 2) + h * 8;
#pragma unroll
                for (int ns = 0; ns < 2; ns++) {
                    int col = nc * 64 + wcol * 16 + ns * 8 + (lane & 3) * 2;
                    *(float2*)(dst + s * DD + col) =
                        make_float2(acc2[ms][ns][h * 2], acc2[ms][ns][h * 2 + 1]);
                }
            }
        }
        __syncthreads();
    }
}

// ---------------- launch -----------------------------------------------------
extern "C" void kernel_launch(void* const* d_in, const int* in_sizes, int n_in,
                              void* d_out, int out_size)
{
    const float* x  = (const float*)d_in[0];
    const float* Wq = (const float*)d_in[1];
    const float* bq = (const float*)d_in[2];
    const float* Wk = (const float*)d_in[3];
    const float* bk = (const float*)d_in[4];
    const float* Wv = (const float*)d_in[5];
    const float* bv = (const float*)d_in[6];
    const float* Wo = (const float*)d_in[7];
    const float* bo = (const float*)d_in[8];
    float* out = (float*)d_out;

    bf16 *qh,*ql,*kh,*kl,*vh,*vl,*xh,*xl,*ah,*al,*wth,*wtl;
    float *E, *O;
    cudaGetSymbolAddress((void**)&qh, g_qh); cudaGetSymbolAddress((void**)&ql, g_ql);
    cudaGetSymbolAddress((void**)&kh, g_kh); cudaGetSymbolAddress((void**)&kl, g_kl);
    cudaGetSymbolAddress((void**)&vh, g_vh); cudaGetSymbolAddress((void**)&vl, g_vl);
    cudaGetSymbolAddress((void**)&xh, g_xh); cudaGetSymbolAddress((void**)&xl, g_xl);
    cudaGetSymbolAddress((void**)&ah, g_ah); cudaGetSymbolAddress((void**)&al, g_al);
    cudaGetSymbolAddress((void**)&wth, g_wth); cudaGetSymbolAddress((void**)&wtl, g_wtl);
    cudaGetSymbolAddress((void**)&E, g_E); cudaGetSymbolAddress((void**)&O, g_O);

    cudaFuncSetAttribute(gemm_mma<0>, cudaFuncAttributeMaxDynamicSharedMemorySize, GEMM_SMEM);
    cudaFuncSetAttribute(gemm_mma<1>, cudaFuncAttributeMaxDynamicSharedMemorySize, GEMM_SMEM);
    cudaFuncSetAttribute(window_attn_mma, cudaFuncAttributeMaxDynamicSharedMemorySize, ATT_SMEM);

    dim3 tb(32, 8);
    dim3 tg(32, 32);
    const float* Ws[4] = {Wq, Wk, Wv, Wo};
    for (int i = 0; i < 4; i++)
        transpose_split<<<tg, tb>>>(Ws[i], wth + (long)i * DD * DD, wtl + (long)i * DD * DD);

    split_x<<<2048, 256>>>((const float4*)x, (uint2*)xh, (uint2*)xl, BSD / 4);
    zero_f4<<<2048, 256>>>((float4*)O, BSD / 4);

    dim3 ggrid(DD / 128, MM / 128);
    gemm_mma<1><<<ggrid, 256, GEMM_SMEM>>>(xh, xl, wth + 0L*DD*DD, wtl + 0L*DD*DD, bq, nullptr, qh, ql);
    gemm_mma<1><<<ggrid, 256, GEMM_SMEM>>>(xh, xl, wth + 1L*DD*DD, wtl + 1L*DD*DD, bk, nullptr, kh, kl);
    gemm_mma<1><<<ggrid, 256, GEMM_SMEM>>>(xh, xl, wth + 2L*DD*DD, wtl + 2L*DD*DD, bv, nullptr, vh, vl);

    window_attn_mma<<<dim3(NW, BB), 256, ATT_SMEM>>>(qh, ql, kh, kl, vh, vl, E, O);

    combine_split<<<2048, 256>>>((const float4*)E, (const float4*)O, (uint2*)ah, (uint2*)al, BSD / 4);
    gemm_mma<0><<<ggrid, 256, GEMM_SMEM>>>(ah, al, wth + 3L*DD*DD, wtl + 3L*DD*DD, bo, out, nullptr, nullptr);
}

// round 5
// speedup vs baseline: 3.8032x; 1.5764x over previous
#include <cuda_runtime.h>
#include <cuda_fp16.h>
#include <cstdint>
#include <math.h>

// Fixed shapes: B=4, S=4096, D=1024, WINDOW=128, stride 64
#define BB   4
#define SS   4096
#define DD   1024
#define NW   63
#define MM   (BB*SS)         // 16384
#define BSD  (BB*SS*DD)      // 16,777,216

typedef __half fp16;

// ---------------- scratch (device globals; no allocation allowed) ----------
__device__ fp16 g_qh[BSD]; __device__ fp16 g_ql[BSD];
__device__ fp16 g_kh[BSD];
__device__ fp16 g_vh[BSD];
__device__ fp16 g_xh[BSD]; __device__ fp16 g_xl[BSD];
__device__ fp16 g_ah[BSD]; __device__ fp16 g_al[BSD];
__device__ fp16 g_wth[4][DD*DD];    // transposed weights hi [N,K]
__device__ float g_E[BSD];
__device__ float g_O[BSD];

// ---------------- helpers ----------------------------------------------------
__device__ __forceinline__ uint32_t smem_u32(const void* p) {
    uint32_t a;
    asm("{ .reg .u64 t; cvta.to.shared.u64 t, %1; cvt.u32.u64 %0, t; }" : "=r"(a) : "l"(p));
    return a;
}
__device__ __forceinline__ float ex2(float x) {
    float y; asm("ex2.approx.f32 %0, %1;" : "=f"(y) : "f"(x)); return y;
}

#define SW128(off) ((off) ^ (((off) >> 3) & 0x70))

#define CP16(dst, src) \
    asm volatile("cp.async.cg.shared.global [%0], [%1], 16;" \
        :: "r"(dst), "l"(__cvta_generic_to_global(src)) : "memory")

#define LDSM_X4(r, a) \
    asm volatile("ldmatrix.sync.aligned.m8n8.x4.shared.b16 {%0,%1,%2,%3}, [%4];" \
        : "=r"((r)[0]), "=r"((r)[1]), "=r"((r)[2]), "=r"((r)[3]) : "r"(a))

#define LDSM_X4T(r, a) \
    asm volatile("ldmatrix.sync.aligned.m8n8.x4.trans.shared.b16 {%0,%1,%2,%3}, [%4];" \
        : "=r"((r)[0]), "=r"((r)[1]), "=r"((r)[2]), "=r"((r)[3]) : "r"(a))

#define MMA16816(c, a, b0, b1) \
    asm volatile("mma.sync.aligned.m16n8k16.row.col.f32.f16.f16.f32 " \
        "{%0,%1,%2,%3}, {%4,%5,%6,%7}, {%8,%9}, {%0,%1,%2,%3};" \
        : "+f"((c)[0]), "+f"((c)[1]), "+f"((c)[2]), "+f"((c)[3]) \
        : "r"((a)[0]), "r"((a)[1]), "r"((a)[2]), "r"((a)[3]), "r"(b0), "r"(b1))

__device__ __forceinline__ uint32_t pk2h(fp16 a, fp16 b) {
    __half2 t = __halves2half2(a, b);
    return *reinterpret_cast<uint32_t*>(&t);
}
__device__ __forceinline__ void split1(float v, fp16 &h, fp16 &l) {
    h = __float2half_rn(v);
    l = __float2half_rn(v - __half2float(h));
}

// ---------------- small kernels ---------------------------------------------
__global__ void split_x(const float4* __restrict__ in, uint2* __restrict__ hi,
                        uint2* __restrict__ lo, int n4) {
    int i = blockIdx.x * blockDim.x + threadIdx.x;
    int st = gridDim.x * blockDim.x;
    for (; i < n4; i += st) {
        float4 v = in[i];
        fp16 h0,h1,h2,h3,l0,l1,l2,l3;
        split1(v.x,h0,l0); split1(v.y,h1,l1); split1(v.z,h2,l2); split1(v.w,h3,l3);
        hi[i] = make_uint2(pk2h(h0,h1), pk2h(h2,h3));
        lo[i] = make_uint2(pk2h(l0,l1), pk2h(l2,l3));
    }
}

// final = (E + O) * countscale, split to fp16 hi/lo; edge rows use E only
__global__ void combine_split(const float4* __restrict__ E, const float4* __restrict__ O,
                              uint2* __restrict__ hi, uint2* __restrict__ lo, int n4) {
    int i = blockIdx.x * blockDim.x + threadIdx.x;
    int st = gridDim.x * blockDim.x;
    for (; i < n4; i += st) {
        int s = (i >> 8) & (SS - 1);
        bool edge = (s < 64) || (s >= SS - 64);
        float4 e = E[i];
        float4 o = edge ? make_float4(0.f,0.f,0.f,0.f) : O[i];
        float sc = edge ? 1.f : 0.5f;
        float4 v = make_float4((e.x+o.x)*sc, (e.y+o.y)*sc, (e.z+o.z)*sc, (e.w+o.w)*sc);
        fp16 h0,h1,h2,h3,l0,l1,l2,l3;
        split1(v.x,h0,l0); split1(v.y,h1,l1); split1(v.z,h2,l2); split1(v.w,h3,l3);
        hi[i] = make_uint2(pk2h(h0,h1), pk2h(h2,h3));
        lo[i] = make_uint2(pk2h(l0,l1), pk2h(l2,l3));
    }
}

// W[K,N] fp32 -> Wt[N,K] fp16 hi
__global__ void transpose_h(const float* __restrict__ W, fp16* __restrict__ hi) {
    __shared__ float tl[32][33];
    int bx = blockIdx.x * 32, by = blockIdx.y * 32;
    int tx = threadIdx.x, ty = threadIdx.y;
#pragma unroll
    for (int r = 0; r < 32; r += 8)
        tl[ty + r][tx] = W[(long)(by + ty + r) * DD + bx + tx];
    __syncthreads();
#pragma unroll
    for (int r = 0; r < 32; r += 8)
        hi[(long)(bx + ty + r) * DD + by + tx] = __float2half_rn(tl[tx][ty + r]);
}

// ---------------- mma.sync fp16 2-pass GEMM ----------------------------------
// C[M,N] = (Ah+Al)[M,K] * Bh^T[N,K] + bias
// OMODE 0: fp32 out.  OMODE 1: fp16 hi/lo out.  OMODE 2: fp16 hi out.
#define GEMM_SMEM 98304

template<int OMODE>
__global__ void __launch_bounds__(256, 2) gemm_mma(
    const fp16* __restrict__ Ah, const fp16* __restrict__ Al,
    const fp16* __restrict__ Bh,
    const float* __restrict__ bias, float* __restrict__ C,
    fp16* __restrict__ Chi, fp16* __restrict__ Clo)
{
    extern __shared__ char smem[];
    const uint32_t sb = smem_u32(smem);
    const int t = threadIdx.x;
    const int lane = t & 31, wid = t >> 5;
    const int wrow = wid & 1;
    const int wcol = wid >> 1;
    const long m0 = (long)blockIdx.y * 128;
    const int  n0 = blockIdx.x * 128;

    const uint32_t sAh[2] = { sb,         sb + 16384 };
    const uint32_t sAl[2] = { sb + 32768, sb + 49152 };
    const uint32_t sB[2]  = { sb + 65536, sb + 81920 };

    int rowg[4]; uint32_t dsts[4];
#pragma unroll
    for (int i = 0; i < 4; i++) {
        int u = t + 256 * i;
        rowg[i] = u >> 3;
        dsts[i] = SW128((u >> 3) * 128 + (u & 7) * 16);
    }
    const int kcol8 = (t & 7) * 8;

    uint32_t a_rowoff[4], a_swz[4];
#pragma unroll
    for (int ms = 0; ms < 4; ms++) {
        int row = wrow * 64 + ms * 16 + (lane & 15);
        a_rowoff[ms] = row * 128;
        a_swz[ms]    = (row & 7) * 16;
    }
    const uint32_t a_kext = (lane >> 4) * 16;
    uint32_t b_rowoff[2], b_swz[2];
#pragma unroll
    for (int np = 0; np < 2; np++) {
        int row = wcol * 32 + np * 16 + ((lane >> 4) & 1) * 8 + (lane & 7);
        b_rowoff[np] = row * 128;
        b_swz[np]    = (row & 7) * 16;
    }
    const uint32_t b_kext = ((lane >> 3) & 1) * 16;

    float acc[4][4][4];
#pragma unroll
    for (int i = 0; i < 4; i++)
#pragma unroll
        for (int j = 0; j < 4; j++)
#pragma unroll
            for (int r = 0; r < 4; r++) acc[i][j][r] = 0.f;

    auto load_chunk = [&](int c, int buf) {
        int kc = c * 64;
        const fp16* Abh = Ah + kc + kcol8;
        const fp16* Abl = Al + kc + kcol8;
        const fp16* Bb  = Bh + kc + kcol8;
#pragma unroll
        for (int i = 0; i < 4; i++) CP16(sAh[buf] + dsts[i], Abh + (m0 + rowg[i]) * DD);
#pragma unroll
        for (int i = 0; i < 4; i++) CP16(sAl[buf] + dsts[i], Abl + (m0 + rowg[i]) * DD);
#pragma unroll
        for (int i = 0; i < 4; i++) CP16(sB[buf]  + dsts[i], Bb  + (long)(n0 + rowg[i]) * DD);
        asm volatile("cp.async.commit_group;" ::: "memory");
    };

    load_chunk(0, 0);

    for (int c = 0; c < 16; c++) {
        const int buf = c & 1;
        if (c + 1 < 16) {
            load_chunk(c + 1, buf ^ 1);
            asm volatile("cp.async.wait_group 1;" ::: "memory");
        } else {
            asm volatile("cp.async.wait_group 0;" ::: "memory");
        }
        __syncthreads();

#pragma unroll
        for (int k16 = 0; k16 < 4; k16++) {
            const uint32_t kb = k16 * 32;
            uint32_t bfr[2][4];
#pragma unroll
            for (int np = 0; np < 2; np++)
                LDSM_X4(bfr[np], sB[buf] + b_rowoff[np] + ((kb + b_kext) ^ b_swz[np]));
#pragma unroll
            for (int pass = 0; pass < 2; pass++) {
                const uint32_t bA = pass ? sAl[buf] : sAh[buf];
                uint32_t afr[4][4];
#pragma unroll
                for (int ms = 0; ms < 4; ms++)
                    LDSM_X4(afr[ms], bA + a_rowoff[ms] + ((kb + a_kext) ^ a_swz[ms]));
#pragma unroll
                for (int ms = 0; ms < 4; ms++)
#pragma unroll
                    for (int ns = 0; ns < 4; ns++)
                        MMA16816(acc[ms][ns], afr[ms],
                                 bfr[ns >> 1][(ns & 1) * 2], bfr[ns >> 1][(ns & 1) * 2 + 1]);
            }
        }
        __syncthreads();
    }

#pragma unroll
    for (int ms = 0; ms < 4; ms++) {
        long r0 = m0 + wrow * 64 + ms * 16 + (lane >> 2);
#pragma unroll
        for (int ns = 0; ns < 4; ns++) {
            int col = n0 + wcol * 32 + ns * 8 + (lane & 3) * 2;
            float2 bv = *(const float2*)(bias + col);
            float v00 = acc[ms][ns][0] + bv.x, v01 = acc[ms][ns][1] + bv.y;
            float v10 = acc[ms][ns][2] + bv.x, v11 = acc[ms][ns][3] + bv.y;
            if (OMODE == 0) {
                *(float2*)(C + r0 * DD + col)       = make_float2(v00, v01);
                *(float2*)(C + (r0 + 8) * DD + col) = make_float2(v10, v11);
            } else if (OMODE == 1) {
                fp16 h0,h1,l0,l1;
                split1(v00, h0, l0); split1(v01, h1, l1);
                *(uint32_t*)(Chi + r0 * DD + col) = pk2h(h0, h1);
                *(uint32_t*)(Clo + r0 * DD + col) = pk2h(l0, l1);
                split1(v10, h0, l0); split1(v11, h1, l1);
                *(uint32_t*)(Chi + (r0 + 8) * DD + col) = pk2h(h0, h1);
                *(uint32_t*)(Clo + (r0 + 8) * DD + col) = pk2h(l0, l1);
            } else {
                *(uint32_t*)(Chi + r0 * DD + col) =
                    pk2h(__float2half_rn(v00), __float2half_rn(v01));
                *(uint32_t*)(Chi + (r0 + 8) * DD + col) =
                    pk2h(__float2half_rn(v10), __float2half_rn(v11));
            }
        }
    }
}

// ---------------- windowed attention via mma.sync (fp16, 2-pass) -------------
// One CTA per (window, batch): 128 q x 128 k over d=1024.
#define ATT_PHI   98304
#define ATT_PLO   131072
#define ATT_RED   163840
#define ATT_SMEM  165888

__global__ void __launch_bounds__(256, 1) window_attn_mma(
    const fp16* __restrict__ qh, const fp16* __restrict__ ql,
    const fp16* __restrict__ kh, const fp16* __restrict__ vh,
    float* __restrict__ Ebuf, float* __restrict__ Obuf)
{
    extern __shared__ char smem[];
    const uint32_t sb = smem_u32(smem);
    const int t = threadIdx.x;
    const int lane = t & 31, wid = t >> 5;
    const int wrow = wid & 1;
    const int wcol = wid >> 1;
    const int w = blockIdx.x, b = blockIdx.y;
    const long qbase = ((long)b * SS + w * 64) * DD;

    const uint32_t sQh[2] = { sb,         sb + 16384 };
    const uint32_t sQl[2] = { sb + 32768, sb + 49152 };
    const uint32_t sK[2]  = { sb + 65536, sb + 81920 };
    const uint32_t vbf[2] = { sb,         sb + 16384 };

    int rowg[4]; uint32_t dsts[4];
#pragma unroll
    for (int i = 0; i < 4; i++) {
        int u = t + 256 * i;
        rowg[i] = u >> 3;
        dsts[i] = SW128((u >> 3) * 128 + (u & 7) * 16);
    }
    const int kcol8 = (t & 7) * 8;

    uint32_t a_rowoff[4], a_swz[4];
#pragma unroll
    for (int ms = 0; ms < 4; ms++) {
        int row = wrow * 64 + ms * 16 + (lane & 15);
        a_rowoff[ms] = row * 128;
        a_swz[ms]    = (row & 7) * 16;
    }
    const uint32_t a_kext = (lane >> 4) * 16;
    uint32_t b_rowoff[2], b_swz[2];
#pragma unroll
    for (int np = 0; np < 2; np++) {
        int row = wcol * 32 + np * 16 + ((lane >> 4) & 1) * 8 + (lane & 7);
        b_rowoff[np] = row * 128;
        b_swz[np]    = (row & 7) * 16;
    }
    const uint32_t b_kext = ((lane >> 3) & 1) * 16;

    float acc[4][4][4];
#pragma unroll
    for (int i = 0; i < 4; i++)
#pragma unroll
        for (int j = 0; j < 4; j++)
#pragma unroll
            for (int r = 0; r < 4; r++) acc[i][j][r] = 0.f;

    auto load_qk = [&](int c, int buf) {
        int kc = c * 64;
        const fp16* Abh = qh + qbase + kc + kcol8;
        const fp16* Abl = ql + qbase + kc + kcol8;
        const fp16* Bb  = kh + qbase + kc + kcol8;
#pragma unroll
        for (int i = 0; i < 4; i++) CP16(sQh[buf] + dsts[i], Abh + (long)rowg[i] * DD);
#pragma unroll
        for (int i = 0; i < 4; i++) CP16(sQl[buf] + dsts[i], Abl + (long)rowg[i] * DD);
#pragma unroll
        for (int i = 0; i < 4; i++) CP16(sK[buf]  + dsts[i], Bb  + (long)rowg[i] * DD);
        asm volatile("cp.async.commit_group;" ::: "memory");
    };

    load_qk(0, 0);

    for (int c = 0; c < 16; c++) {
        const int buf = c & 1;
        if (c + 1 < 16) {
            load_qk(c + 1, buf ^ 1);
            asm volatile("cp.async.wait_group 1;" ::: "memory");
        } else {
            asm volatile("cp.async.wait_group 0;" ::: "memory");
        }
        __syncthreads();

#pragma unroll
        for (int k16 = 0; k16 < 4; k16++) {
            const uint32_t kb = k16 * 32;
            uint32_t bfr[2][4];
#pragma unroll
            for (int np = 0; np < 2; np++)
                LDSM_X4(bfr[np], sK[buf] + b_rowoff[np] + ((kb + b_kext) ^ b_swz[np]));
#pragma unroll
            for (int pass = 0; pass < 2; pass++) {
                const uint32_t bA = pass ? sQl[buf] : sQh[buf];
                uint32_t afr[4][4];
#pragma unroll
                for (int ms = 0; ms < 4; ms++)
                    LDSM_X4(afr[ms], bA + a_rowoff[ms] + ((kb + a_kext) ^ a_swz[ms]));
#pragma unroll
                for (int ms = 0; ms < 4; ms++)
#pragma unroll
                    for (int ns = 0; ns < 4; ns++)
                        MMA16816(acc[ms][ns], afr[ms],
                                 bfr[ns >> 1][(ns & 1) * 2], bfr[ns >> 1][(ns & 1) * 2 + 1]);
            }
        }
        __syncthreads();
    }

    // prefetch V chunk 0 into freed buf0 region while softmax runs
    auto load_v = [&](int nc, int buf) {
        const fp16* Vh = vh + qbase + nc * 64 + kcol8;
#pragma unroll
        for (int i = 0; i < 4; i++) CP16(vbf[buf] + dsts[i], Vh + (long)rowg[i] * DD);
        asm volatile("cp.async.commit_group;" ::: "memory");
    };
    load_v(0, 0);

    // ---- softmax (no max-sub; |score|*0.18 small), cross-warp row sums
    const float CEXP = 0.1803368801f;
    float* red = (float*)(smem + ATT_RED);   // [4][128]
    float ps[4][2];
#pragma unroll
    for (int ms = 0; ms < 4; ms++) {
        ps[ms][0] = 0.f; ps[ms][1] = 0.f;
#pragma unroll
        for (int ns = 0; ns < 4; ns++) {
#pragma unroll
            for (int r = 0; r < 4; r++) {
                float e = ex2(acc[ms][ns][r] * CEXP);
                acc[ms][ns][r] = e;
                ps[ms][r >> 1] += e;
            }
        }
    }
#pragma unroll
    for (int off = 1; off < 4; off <<= 1)
#pragma unroll
        for (int ms = 0; ms < 4; ms++) {
            ps[ms][0] += __shfl_xor_sync(0xffffffffu, ps[ms][0], off);
            ps[ms][1] += __shfl_xor_sync(0xffffffffu, ps[ms][1], off);
        }
    if ((lane & 3) == 0) {
#pragma unroll
        for (int ms = 0; ms < 4; ms++)
#pragma unroll
            for (int h = 0; h < 2; h++) {
                int row = wrow * 64 + ms * 16 + (lane >> 2) + h * 8;
                red[wcol * 128 + row] = ps[ms][h];
            }
    }
    __syncthreads();

    // normalize + store P (fp16 hi/lo) into SW128 chunked layout
#pragma unroll
    for (int ms = 0; ms < 4; ms++) {
#pragma unroll
        for (int h = 0; h < 2; h++) {
            int row = wrow * 64 + ms * 16 + (lane >> 2) + h * 8;
            float s = red[row] + red[128 + row] + red[256 + row] + red[384 + row];
            float inv = 1.f / s;
#pragma unroll
            for (int ns = 0; ns < 4; ns++) {
                int col = wcol * 32 + ns * 8 + (lane & 3) * 2;
                float p0 = acc[ms][ns][h * 2]     * inv;
                float p1 = acc[ms][ns][h * 2 + 1] * inv;
                fp16 h0, l0, h1, l1;
                split1(p0, h0, l0); split1(p1, h1, l1);
                uint32_t off = (col >> 6) * 16384 + SW128(row * 128 + (col & 63) * 2);
                *(uint32_t*)(smem + ATT_PHI + off) = pk2h(h0, h1);
                *(uint32_t*)(smem + ATT_PLO + off) = pk2h(l0, l1);
            }
        }
    }
    __syncthreads();

    // ---- phase 2: O = (Ph+Pl) * Vh over 16 n-chunks of 64 cols
    const int r0v = (lane & 7) + ((lane >> 3) & 1) * 8;
    const uint32_t b2_row = (uint32_t)r0v * 128;
    const uint32_t b2_cs  = ((wcol * 16 + (lane >> 4) * 8) * 2) ^ ((r0v & 7) * 16);

    float* dst = (w & 1) ? Obuf : Ebuf;
    const long rowbase = (long)b * SS + w * 64 + wrow * 64;

    for (int nc = 0; nc < 16; nc++) {
        const int buf = nc & 1;
        if (nc + 1 < 16) {
            load_v(nc + 1, buf ^ 1);
            asm volatile("cp.async.wait_group 1;" ::: "memory");
        } else {
            asm volatile("cp.async.wait_group 0;" ::: "memory");
        }
        __syncthreads();

        float acc2[4][2][4];
#pragma unroll
        for (int i = 0; i < 4; i++)
#pragma unroll
            for (int j = 0; j < 2; j++)
#pragma unroll
                for (int r = 0; r < 4; r++) acc2[i][j][r] = 0.f;

#pragma unroll
        for (int k16 = 0; k16 < 8; k16++) {
            const uint32_t pchunk = (k16 >> 2) * 16384;
            const uint32_t kb = (k16 & 3) * 32;
            uint32_t bfr[4];
            LDSM_X4T(bfr, vbf[buf] + b2_row + (uint32_t)k16 * 2048 + b2_cs);
#pragma unroll
            for (int pass = 0; pass < 2; pass++) {
                const uint32_t Pb = sb + (pass ? ATT_PLO : ATT_PHI);
                uint32_t afr[4][4];
#pragma unroll
                for (int ms = 0; ms < 4; ms++)
                    LDSM_X4(afr[ms], Pb + pchunk + a_rowoff[ms] + ((kb + a_kext) ^ a_swz[ms]));
#pragma unroll
                for (int ms = 0; ms < 4; ms++) {
                    MMA16816(acc2[ms][0], afr[ms], bfr[0], bfr[1]);
                    MMA16816(acc2[ms][1], afr[ms], bfr[2], bfr[3]);
                }
            }
        }

#pragma unroll
        for (int ms = 0; ms < 4; ms++) {
#pragma unroll
            for (int h = 0; h < 2; h++) {
                long s = rowbase + ms * 16 + (lane >> 2) + h * 8;
#pragma unroll
                for (int ns = 0; ns < 2; ns++) {
                    int col = nc * 64 + wcol * 16 + ns * 8 + (lane & 3) * 2;
                    *(float2*)(dst + s * DD + col) =
                        make_float2(acc2[ms][ns][h * 2], acc2[ms][ns][h * 2 + 1]);
                }
            }
        }
        __syncthreads();
    }
}

// ---------------- launch -----------------------------------------------------
extern "C" void kernel_launch(void* const* d_in, const int* in_sizes, int n_in,
                              void* d_out, int out_size)
{
    const float* x  = (const float*)d_in[0];
    const float* Wq = (const float*)d_in[1];
    const float* bq = (const float*)d_in[2];
    const float* Wk = (const float*)d_in[3];
    const float* bk = (const float*)d_in[4];
    const float* Wv = (const float*)d_in[5];
    const float* bv = (const float*)d_in[6];
    const float* Wo = (const float*)d_in[7];
    const float* bo = (const float*)d_in[8];
    float* out = (float*)d_out;

    fp16 *qh,*ql,*kh,*vh,*xh,*xl,*ah,*al,*wth;
    float *E, *O;
    cudaGetSymbolAddress((void**)&qh, g_qh); cudaGetSymbolAddress((void**)&ql, g_ql);
    cudaGetSymbolAddress((void**)&kh, g_kh);
    cudaGetSymbolAddress((void**)&vh, g_vh);
    cudaGetSymbolAddress((void**)&xh, g_xh); cudaGetSymbolAddress((void**)&xl, g_xl);
    cudaGetSymbolAddress((void**)&ah, g_ah); cudaGetSymbolAddress((void**)&al, g_al);
    cudaGetSymbolAddress((void**)&wth, g_wth);
    cudaGetSymbolAddress((void**)&E, g_E); cudaGetSymbolAddress((void**)&O, g_O);

    cudaFuncSetAttribute(gemm_mma<0>, cudaFuncAttributeMaxDynamicSharedMemorySize, GEMM_SMEM);
    cudaFuncSetAttribute(gemm_mma<1>, cudaFuncAttributeMaxDynamicSharedMemorySize, GEMM_SMEM);
    cudaFuncSetAttribute(gemm_mma<2>, cudaFuncAttributeMaxDynamicSharedMemorySize, GEMM_SMEM);
    cudaFuncSetAttribute(window_attn_mma, cudaFuncAttributeMaxDynamicSharedMemorySize, ATT_SMEM);

    dim3 tb(32, 8);
    dim3 tg(32, 32);
    transpose_h<<<tg, tb>>>(Wq, wth + 0L * DD * DD);
    transpose_h<<<tg, tb>>>(Wk, wth + 1L * DD * DD);
    transpose_h<<<tg, tb>>>(Wv, wth + 2L * DD * DD);
    transpose_h<<<tg, tb>>>(Wo, wth + 3L * DD * DD);

    split_x<<<2048, 256>>>((const float4*)x, (uint2*)xh, (uint2*)xl, BSD / 4);

    dim3 ggrid(DD / 128, MM / 128);
    gemm_mma<1><<<ggrid, 256, GEMM_SMEM>>>(xh, xl, wth + 0L*DD*DD, bq, nullptr, qh, ql);
    gemm_mma<2><<<ggrid, 256, GEMM_SMEM>>>(xh, xl, wth + 1L*DD*DD, bk, nullptr, kh, nullptr);
    gemm_mma<2><<<ggrid, 256, GEMM_SMEM>>>(xh, xl, wth + 2L*DD*DD, bv, nullptr, vh, nullptr);

    window_attn_mma<<<dim3(NW, BB), 256, ATT_SMEM>>>(qh, ql, kh, vh, E, O);

    combine_split<<<2048, 256>>>((const float4*)E, (const float4*)O, (uint2*)ah, (uint2*)al, BSD / 4);
    gemm_mma<0><<<ggrid, 256, GEMM_SMEM>>>(ah, al, wth + 3L*DD*DD, bo, out, nullptr, nullptr);
}